// round 12
// baseline (speedup 1.0000x reference)
#include <cuda_runtime.h>
#include <math.h>

#define BB   4
#define SS   2048
#define DIN  1024
#define NH   4          // kv heads
#define HD   64
#define NQ   256        // NH*HD
#define MR   (BB*SS)    // 8192 rows

typedef unsigned long long u64;

// ---- packed fp32x2 helpers (Blackwell FFMA2 path; ptxas never emits these from C++) ----
__device__ __forceinline__ void ffma2(u64 &d, u64 a, u64 b) {
    asm("fma.rn.f32x2 %0, %1, %2, %0;" : "+l"(d) : "l"(a), "l"(b));
}
__device__ __forceinline__ void fmul2(u64 &d, u64 a) {
    asm("mul.rn.f32x2 %0, %0, %1;" : "+l"(d) : "l"(a));
}
__device__ __forceinline__ u64 splat2(float x) {
    u64 r; asm("mov.b64 %0, {%1, %1};" : "=l"(r) : "f"(x)); return r;
}
__device__ __forceinline__ float2 unpack2(u64 v) {
    float2 r; asm("mov.b64 {%0, %1}, %2;" : "=f"(r.x), "=f"(r.y) : "l"(v)); return r;
}

// -------- scratch (device globals; no allocation allowed) --------
__device__ float g_WqEff[DIN * NQ];   // 1 MB
__device__ float g_Q [MR * NQ];       // 8 MB
__device__ float g_K [MR * NQ];       // 8 MB
__device__ float g_V [MR * NQ];       // 8 MB
__device__ float g_AO[MR * NQ];       // 8 MB

// ============================================================
// Wq group-sum: Wq[1024,16,64] -> Wq_eff[1024,4,64]
// ============================================================
__global__ void wq_reduce_kernel(const float* __restrict__ Wq) {
    int idx = blockIdx.x * blockDim.x + threadIdx.x;
    if (idx >= DIN * NQ) return;
    int i = idx >> 8;
    int n = idx & 255;
    int h = n >> 6, d = n & 63;
    const float* p = Wq + (size_t)i * 1024 + (h * 4) * 64 + d;
    g_WqEff[idx] = (p[0] + p[64]) + (p[128] + p[192]);
}

// ============================================================
// SGEMM: C[M,N] = A[M,K] * B[K,N], 128x128 tile, BK=8,
// 256 threads, 8x8 micro-tile, packed f32x2 accumulation.
// M % 128 == 0, N % 128 == 0, K % 8 == 0.
// ============================================================
__global__ void __launch_bounds__(256, 2)
gemm_kernel(const float* __restrict__ A, const float* __restrict__ Bm,
            float* __restrict__ C, int K, int N) {
    __shared__ float Ast[8][136];   // A^T tile: [k][m], padded
    __shared__ float Bs [8][128];   // B tile:  [k][n]
    int tid = threadIdx.x;
    int tx = tid & 15, ty = tid >> 4;           // tx -> 8 cols, ty -> 8 rows
    int bm = blockIdx.y << 7, bn = blockIdx.x << 7;

    int arow = tid >> 1;            // 0..127
    int ak4  = (tid & 1) << 2;      // 0,4
    int brow = tid >> 5;            // 0..7
    int bc4  = (tid & 31) << 2;     // 0..124

    u64 acc[8][4];
    #pragma unroll
    for (int i = 0; i < 8; i++)
        #pragma unroll
        for (int j = 0; j < 4; j++) acc[i][j] = 0ULL;

    const float* Aptr = A + (size_t)(bm + arow) * K + ak4;
    const float* Bptr = Bm + (size_t)brow * N + bn + bc4;

    for (int k0 = 0; k0 < K; k0 += 8) {
        float4 av = *reinterpret_cast<const float4*>(Aptr + k0);
        float4 bv = *reinterpret_cast<const float4*>(Bptr + (size_t)k0 * N);
        Ast[ak4 + 0][arow] = av.x;
        Ast[ak4 + 1][arow] = av.y;
        Ast[ak4 + 2][arow] = av.z;
        Ast[ak4 + 3][arow] = av.w;
        *reinterpret_cast<float4*>(&Bs[brow][bc4]) = bv;
        __syncthreads();

        #pragma unroll
        for (int kk = 0; kk < 8; kk++) {
            float4 a0 = *reinterpret_cast<const float4*>(&Ast[kk][ty << 3]);
            float4 a1 = *reinterpret_cast<const float4*>(&Ast[kk][(ty << 3) + 4]);
            ulonglong2 b0 = *reinterpret_cast<const ulonglong2*>(&Bs[kk][tx << 3]);
            ulonglong2 b1 = *reinterpret_cast<const ulonglong2*>(&Bs[kk][(tx << 3) + 4]);
            u64 bp[4] = {b0.x, b0.y, b1.x, b1.y};
            float am[8] = {a0.x, a0.y, a0.z, a0.w, a1.x, a1.y, a1.z, a1.w};
            #pragma unroll
            for (int i = 0; i < 8; i++) {
                u64 s = splat2(am[i]);
                #pragma unroll
                for (int j = 0; j < 4; j++) ffma2(acc[i][j], s, bp[j]);
            }
        }
        __syncthreads();
    }

    #pragma unroll
    for (int i = 0; i < 8; i++) {
        float2 c0 = unpack2(acc[i][0]);
        float2 c1 = unpack2(acc[i][1]);
        float2 c2 = unpack2(acc[i][2]);
        float2 c3 = unpack2(acc[i][3]);
        float* cp = C + (size_t)(bm + (ty << 3) + i) * N + bn + (tx << 3);
        *reinterpret_cast<float4*>(cp)     = make_float4(c0.x, c0.y, c1.x, c1.y);
        *reinterpret_cast<float4*>(cp + 4) = make_float4(c2.x, c2.y, c3.x, c3.y);
    }
}

// ============================================================
// 2-axis RoPE in place on X[MR, NQ].
// ============================================================
__global__ void rope_kernel(float* __restrict__ X, const int* __restrict__ coords) {
    int row = blockIdx.x;
    int t = threadIdx.x;       // 0..127
    int h = t >> 5;
    int m = t & 31;
    int axis = m >> 4, j = m & 15;
    float c = (float)coords[(size_t)row * 2 + axis];
    float inv = (float)exp(-(double)j * (9.210340371976184 / 16.0)); // ln(10000)/16
    float ang = c * inv;
    float sn, cs;
    sincosf(ang, &sn, &cs);
    float* p = X + (size_t)row * NQ + h * HD + 2 * m;
    float x1 = p[0], x2 = p[1];
    p[0] = x1 * cs - x2 * sn;
    p[1] = x1 * sn + x2 * cs;
}

// ============================================================
// Flash attention: per (b,h,qtile64). 256 threads, 4x4 micro,
// packed f32x2 math. QK^T packs along contraction dim d
// (lane0=even-d partial, lane1=odd-d partial, horizontal add at
// the end) so both operands vector-load from row-major smem.
// PV packs along output columns (V pairs natural, P splatted).
// ============================================================
#define SMP 68   // padded row stride (floats); 68*4B=272B, 16B-aligned rows
__global__ void __launch_bounds__(256, 2)
attn_kernel() {
    extern __shared__ float sm[];
    float* Qs = sm;
    float* Ks = sm +     64 * SMP;
    float* Vs = sm + 2 * 64 * SMP;
    float* Ps = sm + 3 * 64 * SMP;

    int bid = blockIdx.x;
    int mt = bid & 31;
    int bh = bid >> 5;
    int h = bh & 3, b = bh >> 2;

    int tid = threadIdx.x;
    int tx = tid & 15, ty = tid >> 4;
    int r0 = ty << 2;              // 4 q-rows
    int c0 = tx << 2;              // 4 kv-cols

    const float* Qg = g_Q + (size_t)b * SS * NQ + h * HD;
    const float* Kg = g_K + (size_t)b * SS * NQ + h * HD;
    const float* Vg = g_V + (size_t)b * SS * NQ + h * HD;

    int s0 = mt << 6;

    // load Q tile [64][64]
    for (int idx = tid; idx < 1024; idx += 256) {
        int r = idx >> 4, c4 = (idx & 15) << 2;
        float4 v = *reinterpret_cast<const float4*>(Qg + (size_t)(s0 + r) * NQ + c4);
        *reinterpret_cast<float4*>(&Qs[r * SMP + c4]) = v;
    }

    float mi[4] = {-1e30f, -1e30f, -1e30f, -1e30f};
    float li[4] = {0.f, 0.f, 0.f, 0.f};
    u64 oa[4][2];
    #pragma unroll
    for (int i = 0; i < 4; i++) { oa[i][0] = 0ULL; oa[i][1] = 0ULL; }

    for (int nt = 0; nt < 32; nt++) {
        __syncthreads();   // prev iter's K/V/P readers done
        int kb = nt << 6;
        for (int idx = tid; idx < 1024; idx += 256) {
            int r = idx >> 4, c4 = (idx & 15) << 2;
            float4 kv = *reinterpret_cast<const float4*>(Kg + (size_t)(kb + r) * NQ + c4);
            *reinterpret_cast<float4*>(&Ks[r * SMP + c4]) = kv;
            float4 vv = *reinterpret_cast<const float4*>(Vg + (size_t)(kb + r) * NQ + c4);
            *reinterpret_cast<float4*>(&Vs[r * SMP + c4]) = vv;
        }
        __syncthreads();

        // ---- S = Q K^T, d-pair-packed accumulation ----
        u64 sa[4][4];
        #pragma unroll
        for (int i = 0; i < 4; i++)
            #pragma unroll
            for (int j = 0; j < 4; j++) sa[i][j] = 0ULL;

        #pragma unroll 2
        for (int d4 = 0; d4 < 64; d4 += 4) {
            ulonglong2 q[4], k[4];
            #pragma unroll
            for (int i = 0; i < 4; i++)
                q[i] = *reinterpret_cast<const ulonglong2*>(&Qs[(r0 + i) * SMP + d4]);
            #pragma unroll
            for (int j = 0; j < 4; j++)
                k[j] = *reinterpret_cast<const ulonglong2*>(&Ks[(c0 + j) * SMP + d4]);
            #pragma unroll
            for (int i = 0; i < 4; i++)
                #pragma unroll
                for (int j = 0; j < 4; j++) {
                    ffma2(sa[i][j], q[i].x, k[j].x);
                    ffma2(sa[i][j], q[i].y, k[j].y);
                }
        }

        // ---- online softmax ----
        #pragma unroll
        for (int i = 0; i < 4; i++) {
            float2 t0 = unpack2(sa[i][0]);
            float2 t1 = unpack2(sa[i][1]);
            float2 t2 = unpack2(sa[i][2]);
            float2 t3 = unpack2(sa[i][3]);
            float v0 = (t0.x + t0.y) * 0.125f;
            float v1 = (t1.x + t1.y) * 0.125f;
            float v2 = (t2.x + t2.y) * 0.125f;
            float v3 = (t3.x + t3.y) * 0.125f;
            float rmax = fmaxf(fmaxf(v0, v1), fmaxf(v2, v3));
            #pragma unroll
            for (int o = 8; o >= 1; o >>= 1)
                rmax = fmaxf(rmax, __shfl_xor_sync(0xffffffffu, rmax, o));
            float mnew = fmaxf(mi[i], rmax);
            float corr = __expf(mi[i] - mnew);
            float p0 = __expf(v0 - mnew);
            float p1 = __expf(v1 - mnew);
            float p2 = __expf(v2 - mnew);
            float p3 = __expf(v3 - mnew);
            float* pr = Ps + (r0 + i) * SMP + c0;
            pr[0] = p0; pr[1] = p1; pr[2] = p2; pr[3] = p3;
            float rsum = (p0 + p1) + (p2 + p3);
            #pragma unroll
            for (int o = 8; o >= 1; o >>= 1)
                rsum += __shfl_xor_sync(0xffffffffu, rsum, o);
            li[i] = li[i] * corr + rsum;
            mi[i] = mnew;
            u64 cs = splat2(corr);
            fmul2(oa[i][0], cs);
            fmul2(oa[i][1], cs);
        }
        __syncthreads();   // P fully written before PV

        // ---- O += P @ V, col-packed ----
        #pragma unroll 4
        for (int j = 0; j < 64; j += 2) {
            ulonglong2 va = *reinterpret_cast<const ulonglong2*>(&Vs[j * SMP + c0]);
            ulonglong2 vb = *reinterpret_cast<const ulonglong2*>(&Vs[(j + 1) * SMP + c0]);
            #pragma unroll
            for (int i = 0; i < 4; i++) {
                float2 p = *reinterpret_cast<const float2*>(&Ps[(r0 + i) * SMP + j]);
                u64 spa = splat2(p.x);
                u64 spb = splat2(p.y);
                ffma2(oa[i][0], spa, va.x);
                ffma2(oa[i][1], spa, va.y);
                ffma2(oa[i][0], spb, vb.x);
                ffma2(oa[i][1], spb, vb.y);
            }
        }
    }

    float* Og = g_AO + (size_t)b * SS * NQ + h * HD;
    #pragma unroll
    for (int i = 0; i < 4; i++) {
        float inv = 1.0f / li[i];
        float2 o0 = unpack2(oa[i][0]);
        float2 o1 = unpack2(oa[i][1]);
        float4 o = make_float4(o0.x * inv, o0.y * inv, o1.x * inv, o1.y * inv);
        *reinterpret_cast<float4*>(Og + (size_t)(s0 + r0 + i) * NQ + c0) = o;
    }
}

// ============================================================
// launch
// ============================================================
extern "C" void kernel_launch(void* const* d_in, const int* in_sizes, int n_in,
                              void* d_out, int out_size) {
    (void)in_sizes; (void)n_in; (void)out_size;
    const float* q  = (const float*)d_in[0];
    const int*   qc = (const int*)  d_in[1];
    const float* kv = (const float*)d_in[2];
    const int*   kc = (const int*)  d_in[3];
    const float* Wq = (const float*)d_in[4];
    const float* Wk = (const float*)d_in[5];
    const float* Wv = (const float*)d_in[6];
    const float* Wo = (const float*)d_in[7];
    float* out = (float*)d_out;

    cudaFuncSetAttribute(attn_kernel, cudaFuncAttributeMaxDynamicSharedMemorySize,
                         4 * 64 * SMP * 4);

    void *pWqEff, *pQ, *pK, *pV, *pAO;
    cudaGetSymbolAddress(&pWqEff, g_WqEff);
    cudaGetSymbolAddress(&pQ,  g_Q);
    cudaGetSymbolAddress(&pK,  g_K);
    cudaGetSymbolAddress(&pV,  g_V);
    cudaGetSymbolAddress(&pAO, g_AO);

    // 1. Wq group-sum
    wq_reduce_kernel<<<(DIN * NQ) / 256, 256>>>(Wq);

    // 2. projections: [8192,1024] x [1024,256]  (128x128 tiles)
    dim3 gproj(NQ / 128, MR / 128);
    gemm_kernel<<<gproj, 256>>>(q,  (const float*)pWqEff, (float*)pQ, DIN, NQ);
    gemm_kernel<<<gproj, 256>>>(kv, Wk,                   (float*)pK, DIN, NQ);
    gemm_kernel<<<gproj, 256>>>(kv, Wv,                   (float*)pV, DIN, NQ);

    // 3. RoPE in place on Q_eff and K
    rope_kernel<<<MR, 128>>>((float*)pQ, qc);
    rope_kernel<<<MR, 128>>>((float*)pK, kc);

    // 4. attention: 16 (b,h) x 32 q-tiles
    attn_kernel<<<16 * 32, 256, 4 * 64 * SMP * 4>>>();

    // 5. output projection: [8192,256] x [256,1024]
    dim3 gout(DIN / 128, MR / 128);
    gemm_kernel<<<gout, 256>>>((const float*)pAO, Wo, out, NQ, DIN);
}